// round 9
// baseline (speedup 1.0000x reference)
#include <cuda_runtime.h>
#include <cuda_bf16.h>
#include <math.h>
#include <stdint.h>

#define HID   1024
#define EMBD  512
#define BATCH 64
#define SEQ   512
#define G4    4096
#define NBLK  128

// ===================== device scratch =====================
__device__ float    g_xproj[(size_t)SEQ * BATCH * G4];     // [t][b][4096]
// W_ih in B-fragment order, bf16 hi/lo (xproj):
__device__ uint32_t g_wihfrag[512 * 32 * 32 * 4];          // 8 MB
// emb rows in A-fragment order, bf16 hi/lo:
__device__ uint4    g_afrag[2048 * 32 * 32 * 2];           // 67 MB
// W_hh int8 digit planes, IMMA m16n8k32 B-fragment order:
//   uint2 idx = ((j*32 + kstep)*4 + g)*32 + lane
__device__ uint2    g_wq1[128 * 32 * 4 * 32];              // 4 MB
__device__ uint2    g_wq2[128 * 32 * 4 * 32];              // 4 MB
// h int8 digit planes, IMMA A-fragment order, double buffered:
//   byte idx = ((kstep*4 + mt)*32 + lane)*16 + reg*4 + jb
__device__ __align__(16) uint8_t g_hq1[2][32 * 4 * 32 * 16];   // 64 KB x2
__device__ __align__(16) uint8_t g_hq2[2][32 * 4 * 32 * 16];
__device__ float    g_hfin[BATCH * HID];
__device__ unsigned g_count;
__device__ unsigned g_wmax_bits;

__global__ void init_kernel() {
    if (blockIdx.x == 0 && threadIdx.x == 0) { g_count = 0u; g_wmax_bits = 0u; }
}

// ===================== helpers =====================
__device__ __forceinline__ float sigmf(float v) { return 1.0f / (1.0f + expf(-v)); }

__device__ __forceinline__ uint32_t pack_bf16x2(float e0, float e1) {
    uint16_t u0 = __bfloat16_as_ushort(__float2bfloat16(e0));
    uint16_t u1 = __bfloat16_as_ushort(__float2bfloat16(e1));
    return (uint32_t)u0 | ((uint32_t)u1 << 16);
}

#define MMA_BF16(d, a, b0, b1) \
    asm volatile("mma.sync.aligned.m16n8k16.row.col.f32.bf16.bf16.f32 " \
        "{%0,%1,%2,%3}, {%4,%5,%6,%7}, {%8,%9}, {%0,%1,%2,%3};" \
        : "+f"((d)[0]), "+f"((d)[1]), "+f"((d)[2]), "+f"((d)[3]) \
        : "r"((a).x), "r"((a).y), "r"((a).z), "r"((a).w), "r"(b0), "r"(b1))

#define MMA_S8(d, a, b) \
    asm volatile("mma.sync.aligned.m16n8k32.row.col.s32.s8.s8.s32 " \
        "{%0,%1,%2,%3}, {%4,%5,%6,%7}, {%8,%9}, {%0,%1,%2,%3};" \
        : "+r"((d)[0]), "+r"((d)[1]), "+r"((d)[2]), "+r"((d)[3]) \
        : "r"((a).x), "r"((a).y), "r"((a).z), "r"((a).w), "r"((b).x), "r"((b).y))

// ===================== W_hh max reduce =====================
__global__ void wmax_kernel(const float* __restrict__ W_hh) {
    int i = blockIdx.x * blockDim.x + threadIdx.x;
    float m = 0.0f;
    for (int k = i; k < 4096 * 1024; k += gridDim.x * blockDim.x)
        m = fmaxf(m, fabsf(W_hh[k]));
#pragma unroll
    for (int o = 16; o; o >>= 1) m = fmaxf(m, __shfl_xor_sync(0xFFFFFFFFu, m, o));
    if ((threadIdx.x & 31) == 0) atomicMax(&g_wmax_bits, __float_as_uint(m));
}

// ===================== W_hh -> int8 digit-plane fragments =====================
// one thread per (j, kstep, g, lane) -> uint2 per plane
__global__ void wqconv_kernel(const float* __restrict__ W_hh) {
    int id = blockIdx.x * blockDim.x + threadIdx.x;   // 128*32*4*32 = 524288
    if (id >= 128 * 32 * 4 * 32) return;
    int lane  = id & 31;
    int g     = (id >> 5) & 3;
    int kstep = (id >> 7) & 31;
    int j     = id >> 12;
    int n = g * 1024 + j * 8 + (lane >> 2);
    float inv = 127.0f / __uint_as_float(g_wmax_bits);

    uint32_t p1[2], p2[2];
#pragma unroll
    for (int khalf = 0; khalf < 2; khalf++) {
        uint32_t w1 = 0, w2 = 0;
#pragma unroll
        for (int jb = 0; jb < 4; jb++) {
            int k = kstep * 32 + khalf * 16 + (lane & 3) * 4 + jb;
            float q = W_hh[(size_t)n * HID + k] * inv;
            int b1 = __float2int_rn(q);
            int b2 = __float2int_rn((q - (float)b1) * 254.0f);
            w1 |= (uint32_t)(b1 & 0xFF) << (jb * 8);
            w2 |= (uint32_t)(b2 & 0xFF) << (jb * 8);
        }
        p1[khalf] = w1; p2[khalf] = w2;
    }
    g_wq1[id] = make_uint2(p1[0], p1[1]);
    g_wq2[id] = make_uint2(p2[0], p2[1]);
}

// ===================== W_ih -> fragment converter (unchanged) =====================
__global__ void wihconv_kernel(const float* __restrict__ W_ih) {
    int id = blockIdx.x * blockDim.x + threadIdx.x;   // 4096*256 k-pairs
    if (id >= 4096 * 256) return;
    int n  = id >> 8;
    int k  = (id & 255) * 2;
    float2 w = *(const float2*)(W_ih + (size_t)n * EMBD + k);
    float hi0 = __bfloat162float(__float2bfloat16(w.x));
    float hi1 = __bfloat162float(__float2bfloat16(w.y));
    uint32_t ph = pack_bf16x2(w.x, w.y);
    uint32_t pl = pack_bf16x2(w.x - hi0, w.y - hi1);

    int ntile = n >> 3, ul = n & 7;
    int s = k >> 4, tig = (k >> 1) & 3, khalf = (k >> 3) & 1;
    int lane = (ul << 2) | tig;
    uint32_t base = (uint32_t)(((ntile * 32 + s) * 32 + lane) * 4);
    g_wihfrag[base + khalf]     = ph;
    g_wihfrag[base + 2 + khalf] = pl;
}

// ===================== embedding gather -> A fragments (unchanged) =====================
__global__ void gather_kernel(const int*   __restrict__ x,
                              const float* __restrict__ emb_table) {
    __shared__ int toks[16];
    const int mtile = blockIdx.x;
    const int tid = threadIdx.x;
    const int wid = tid >> 5;
    const int lid = tid & 31;

    if (tid < 16) {
        int m = mtile * 16 + tid;
        int t = m >> 6, b = m & 63;
        toks[tid] = x[b * SEQ + t];
    }
    __syncthreads();

    const int r0 = lid >> 2;
    const int c0 = (lid & 3) * 2;
    const int tok0 = toks[r0];
    const int tok1 = toks[r0 + 8];
    const float* e0 = emb_table + (size_t)tok0 * EMBD;
    const float* e1 = emb_table + (size_t)tok1 * EMBD;

#pragma unroll
    for (int q = 0; q < 4; q++) {
        int s = wid * 4 + q;
        int kb = s * 16;
        float2 v00 = (tok0 == 0) ? make_float2(0.f, 0.f) : *(const float2*)(e0 + kb + c0);
        float2 v01 = (tok0 == 0) ? make_float2(0.f, 0.f) : *(const float2*)(e0 + kb + c0 + 8);
        float2 v10 = (tok1 == 0) ? make_float2(0.f, 0.f) : *(const float2*)(e1 + kb + c0);
        float2 v11 = (tok1 == 0) ? make_float2(0.f, 0.f) : *(const float2*)(e1 + kb + c0 + 8);

        uint4 hi, lo;
        hi.x = pack_bf16x2(v00.x, v00.y);
        hi.y = pack_bf16x2(v10.x, v10.y);
        hi.z = pack_bf16x2(v01.x, v01.y);
        hi.w = pack_bf16x2(v11.x, v11.y);
        lo.x = pack_bf16x2(v00.x - __bfloat162float(__float2bfloat16(v00.x)),
                           v00.y - __bfloat162float(__float2bfloat16(v00.y)));
        lo.y = pack_bf16x2(v10.x - __bfloat162float(__float2bfloat16(v10.x)),
                           v10.y - __bfloat162float(__float2bfloat16(v10.y)));
        lo.z = pack_bf16x2(v01.x - __bfloat162float(__float2bfloat16(v01.x)),
                           v01.y - __bfloat162float(__float2bfloat16(v01.y)));
        lo.w = pack_bf16x2(v11.x - __bfloat162float(__float2bfloat16(v11.x)),
                           v11.y - __bfloat162float(__float2bfloat16(v11.y)));

        uint4* dst = g_afrag + (((size_t)mtile * 32 + s) * 32 + lid) * 2;
        dst[0] = hi;
        dst[1] = lo;
    }
}

// ===================== xproj GEMM (HMMA, hi/lo split, nf=32) — unchanged ==========
__global__ void __launch_bounds__(256, 1)
xproj_mma(const float* __restrict__ b_ih) {
    const int tid = threadIdx.x;
    const int wid = tid >> 5;
    const int lid = tid & 31;
    const int mtile = blockIdx.x * 8 + wid;
    const int nt0   = blockIdx.y * 32;

    float acc[32][4];
#pragma unroll
    for (int nf = 0; nf < 32; nf++)
#pragma unroll
        for (int c = 0; c < 4; c++) acc[nf][c] = 0.0f;

    const uint4* abase = g_afrag + ((size_t)mtile * 32) * 32 * 2 + lid * 2;
    const uint4* bbase = ((const uint4*)g_wihfrag) + ((size_t)nt0 * 32) * 32 + lid;

    for (int s = 0; s < 32; s++) {
        uint4 Ah = __ldcg(abase + (size_t)s * 64);
        uint4 Al = __ldcg(abase + (size_t)s * 64 + 1);
        const uint4* bp = bbase + (size_t)s * 32;
#pragma unroll
        for (int nf = 0; nf < 32; nf++) {
            uint4 B = __ldg(bp + (size_t)nf * 32 * 32);
            MMA_BF16(acc[nf], Ah, B.x, B.y);
            MMA_BF16(acc[nf], Ah, B.z, B.w);
            MMA_BF16(acc[nf], Al, B.x, B.y);
        }
    }

    const int row0 = mtile * 16 + (lid >> 2);
    const int cbase = (lid & 3) * 2;
    float* o0 = g_xproj + (size_t)row0 * G4;
    float* o1 = g_xproj + (size_t)(row0 + 8) * G4;
#pragma unroll
    for (int nf = 0; nf < 32; nf++) {
        int col = (nt0 + nf) * 8 + cbase;
        float2 bias = *(const float2*)(b_ih + col);
        *(float2*)(o0 + col) = make_float2(acc[nf][0] + bias.x, acc[nf][1] + bias.y);
        *(float2*)(o1 + col) = make_float2(acc[nf][2] + bias.x, acc[nf][3] + bias.y);
    }
}

// ===================== grid barrier (release/acquire) =====================
__device__ __forceinline__ void grid_bar(unsigned target) {
    __syncthreads();
    if (threadIdx.x == 0) {
        asm volatile("red.release.gpu.global.add.u32 [%0], %1;"
                     :: "l"(&g_count), "r"(1u) : "memory");
        unsigned v;
        while (true) {
            asm volatile("ld.acquire.gpu.global.u32 %0, [%1];"
                         : "=r"(v) : "l"(&g_count) : "memory");
            if (v >= target * NBLK) break;
            __nanosleep(32);
        }
    }
    __syncthreads();
}

// ===================== persistent LSTM recurrence (IMMA s8, 16-warp 4-way K-split)
// Block j owns gate cols {g*1024 + j*8 + ul}. Warp wid = kh*4 + mt.
// gates_hW = wmax/127^2 * (D1 + (D2+D3)/254), D = s32 IMMA accumulation.
__global__ void __launch_bounds__(512, 1)
lstm_persistent(const float* __restrict__ b_hh) {
    __shared__ float xs[64][36];
    __shared__ float psum[3][4][16][32];
    __shared__ float bhs[32];

    const int j   = blockIdx.x;
    const int tid = threadIdx.x;
    const int wid = tid >> 5;
    const int lid = tid & 31;
    const int kh  = wid >> 2;              // K-quarter 0..3
    const int mt  = wid & 3;               // m-tile
    const int r0  = mt * 16 + (lid >> 2);
    const int tig = lid & 3;

    const float wmax = __uint_as_float(g_wmax_bits);
    const float gs   = wmax / 16129.0f;    // wmax / 127^2

    if (tid < 32) {
        int g = tid >> 3, ul = tid & 7;
        bhs[tid] = b_hh[g * HID + j * 8 + ul];
    }

    // zero h digit planes, buffer 0 (cooperative across grid)
    {
        int idx = j * 512 + tid;           // 65536 threads, 16384 words/plane
        if (idx < 16384) {
            ((uint32_t*)g_hq1[0])[idx] = 0u;
            ((uint32_t*)g_hq2[0])[idx] = 0u;
        }
    }
    float creg[4];
#pragma unroll
    for (int q = 0; q < 4; q++) creg[q] = 0.0f;

    // precomputed epilogue byte offset (t-invariant)
    const int k0     = 8 * j + 2 * tig;
    const int ekstep = k0 >> 5;
    const int ekc    = k0 & 31;
    const int ekhalf = ekc >> 4;
    const int ek16   = ekc & 15;
    const int eclane = ((lid >> 2) << 2) + (ek16 >> 2);
    const uint32_t offA = (uint32_t)(((ekstep * 4 + mt) * 32 + eclane) * 16
                                     + ekhalf * 8 + (ek16 & 3));

    unsigned barnum = 0;
    grid_bar(++barnum);

    const uint2* wq1base = g_wq1 + ((size_t)(j * 32 + kh * 8) * 4) * 32 + lid;
    const uint2* wq2base = g_wq2 + ((size_t)(j * 32 + kh * 8) * 4) * 32 + lid;

    for (int t = 0; t < SEQ; t++) {
        const int cb = t & 1, nb = cb ^ 1;

        // ---- warps 8-15 stage x_proj tile [64 b x 32 cols] into smem
        if (wid >= 8) {
            int t2 = tid - 256;
            int b = t2 >> 2;
            int g = t2 & 3;
            const float* xp = g_xproj + (size_t)t * BATCH * G4 + (size_t)b * G4
                            + (size_t)g * HID + j * 8;
            float4 v0 = __ldcs((const float4*)xp);
            float4 v1 = __ldcs((const float4*)xp + 1);
            *(float4*)&xs[b][g * 8]     = v0;
            *(float4*)&xs[b][g * 8 + 4] = v1;
        }

        // ---- K-quarter: 8 k32-steps, 3 IMMA per (step, gate)
        const uint4* a1base = (const uint4*)g_hq1[cb] + ((size_t)(kh * 8 * 4 + mt)) * 32 + lid;
        const uint4* a2base = (const uint4*)g_hq2[cb] + ((size_t)(kh * 8 * 4 + mt)) * 32 + lid;

        uint4 A1[3], A2[3];
        uint2 B1[2][4], B2[2][4];
        int am[4][4], ac[4][4];
#pragma unroll
        for (int g = 0; g < 4; g++)
#pragma unroll
            for (int c = 0; c < 4; c++) { am[g][c] = 0; ac[g][c] = 0; }

#pragma unroll
        for (int p = 0; p < 2; p++) {
            A1[p] = __ldcg(a1base + (size_t)p * 128);
            A2[p] = __ldcg(a2base + (size_t)p * 128);
        }
#pragma unroll
        for (int g = 0; g < 4; g++) {
            B1[0][g] = __ldg(wq1base + g * 32);
            B2[0][g] = __ldg(wq2base + g * 32);
        }

#pragma unroll
        for (int s = 0; s < 8; s++) {
            if (s < 7) {
                const uint2* w1p = wq1base + (size_t)(s + 1) * 128;
                const uint2* w2p = wq2base + (size_t)(s + 1) * 128;
#pragma unroll
                for (int g = 0; g < 4; g++) {
                    B1[(s + 1) & 1][g] = __ldg(w1p + g * 32);
                    B2[(s + 1) & 1][g] = __ldg(w2p + g * 32);
                }
            }
            if (s < 6) {
                A1[(s + 2) % 3] = __ldcg(a1base + (size_t)(s + 2) * 128);
                A2[(s + 2) % 3] = __ldcg(a2base + (size_t)(s + 2) * 128);
            }
            uint4 Ad1 = A1[s % 3];
            uint4 Ad2 = A2[s % 3];
#pragma unroll
            for (int g = 0; g < 4; g++) {
                MMA_S8(am[g], Ad1, B1[s & 1][g]);
                MMA_S8(ac[g], Ad1, B2[s & 1][g]);
                MMA_S8(ac[g], Ad2, B1[s & 1][g]);
            }
        }

        // combine digit scales -> float partials
        float gf[4][4];
#pragma unroll
        for (int g = 0; g < 4; g++)
#pragma unroll
            for (int c = 0; c < 4; c++)
                gf[g][c] = (float)am[g][c] + (float)ac[g][c] * (1.0f / 254.0f);

        if (kh >= 1) {
#pragma unroll
            for (int g = 0; g < 4; g++)
#pragma unroll
                for (int c = 0; c < 4; c++)
                    psum[kh - 1][mt][g * 4 + c][lid] = gf[g][c];
        }
        __syncthreads();

        // ---- warps kh==0: reduce + LSTM update + int8 h store
        if (kh == 0) {
#pragma unroll
            for (int q = 0; q < 3; q++)
#pragma unroll
                for (int g = 0; g < 4; g++)
#pragma unroll
                    for (int c = 0; c < 4; c++)
                        gf[g][c] += psum[q][mt][g * 4 + c][lid];

            uint8_t* hq1 = g_hq1[nb] + offA;
            uint8_t* hq2 = g_hq2[nb] + offA;
#pragma unroll
            for (int mh = 0; mh < 2; mh++) {
                int row = r0 + 8 * mh;
                float h2[2];
#pragma unroll
                for (int cbit = 0; cbit < 2; cbit++) {
                    int ci = mh * 2 + cbit;
                    int ul = 2 * tig + cbit;
                    float ig = gs * gf[0][ci] + xs[row][ul]      + bhs[ul];
                    float fg = gs * gf[1][ci] + xs[row][8 + ul]  + bhs[8 + ul];
                    float gg = gs * gf[2][ci] + xs[row][16 + ul] + bhs[16 + ul];
                    float og = gs * gf[3][ci] + xs[row][24 + ul] + bhs[24 + ul];
                    float cn = sigmf(fg) * creg[ci] + sigmf(ig) * tanhf(gg);
                    creg[ci] = cn;
                    h2[cbit] = sigmf(og) * tanhf(cn);
                }
                // two-digit int8 quantization: h = (a1 + a2/254)/127
                float q0 = h2[0] * 127.0f, q1 = h2[1] * 127.0f;
                int a10 = __float2int_rn(q0), a11 = __float2int_rn(q1);
                int a20 = __float2int_rn((q0 - (float)a10) * 254.0f);
                int a21 = __float2int_rn((q1 - (float)a11) * 254.0f);
                *(uint16_t*)(hq1 + mh * 4) =
                    (uint16_t)((a10 & 0xFF) | ((a11 & 0xFF) << 8));
                *(uint16_t*)(hq2 + mh * 4) =
                    (uint16_t)((a20 & 0xFF) | ((a21 & 0xFF) << 8));
                if (t == SEQ - 1) {
                    *(float2*)(g_hfin + row * HID + j * 8 + 2 * tig) =
                        make_float2(h2[0], h2[1]);
                }
            }
        }
        grid_bar(++barnum);
    }
}

// ===================== head (parallel warp-reduce) — unchanged =====================
__global__ void final_kernel(const float* __restrict__ W1,
                             const float* __restrict__ b1,
                             const float* __restrict__ W2,
                             const float* __restrict__ b2,
                             float* __restrict__ out) {
    __shared__ float hidden[64];
    const int b   = blockIdx.x;
    const int tid = threadIdx.x;
    const int wid = tid >> 5;
    const int lid = tid & 31;
    const float* hrow = g_hfin + b * HID;

#pragma unroll
    for (int q = 0; q < 8; q++) {
        int jj = wid + q * 8;
        const float* wrow = W1 + jj * HID;
        float s = 0.0f;
#pragma unroll 8
        for (int k = lid; k < HID; k += 32) s = fmaf(hrow[k], wrow[k], s);
#pragma unroll
        for (int o = 16; o; o >>= 1) s += __shfl_xor_sync(0xFFFFFFFFu, s, o);
        if (lid == 0) hidden[jj] = fmaxf(s + b1[jj], 0.0f) * W2[jj];
    }
    __syncthreads();
    if (wid == 0) {
        float v = hidden[lid] + hidden[lid + 32];
#pragma unroll
        for (int o = 16; o; o >>= 1) v += __shfl_xor_sync(0xFFFFFFFFu, v, o);
        if (lid == 0) out[b] = v + b2[0];
    }
}

// ===================== launch =====================
extern "C" void kernel_launch(void* const* d_in, const int* in_sizes, int n_in,
                              void* d_out, int out_size) {
    (void)in_sizes; (void)n_in; (void)out_size;
    const int*   x         = (const int*)  d_in[0];
    const float* emb_table = (const float*)d_in[2];
    const float* W_ih      = (const float*)d_in[3];
    const float* b_ih      = (const float*)d_in[4];
    const float* W_hh      = (const float*)d_in[5];
    const float* b_hh      = (const float*)d_in[6];
    const float* W1        = (const float*)d_in[7];
    const float* b1        = (const float*)d_in[8];
    const float* W2        = (const float*)d_in[9];
    const float* b2        = (const float*)d_in[10];
    float* out = (float*)d_out;

    init_kernel<<<1, 32>>>();
    wmax_kernel<<<1024, 256>>>(W_hh);
    wqconv_kernel<<<2048, 256>>>(W_hh);
    wihconv_kernel<<<(4096 * 256 + 255) / 256, 256>>>(W_ih);
    gather_kernel<<<2048, 256>>>(x, emb_table);
    xproj_mma<<<dim3(256, 16), 256>>>(b_ih);
    lstm_persistent<<<NBLK, 512>>>(b_hh);
    final_kernel<<<BATCH, 256>>>(W1, b1, W2, b2, out);
}

// round 10
// speedup vs baseline: 2.0558x; 2.0558x over previous
#include <cuda_runtime.h>
#include <cuda_fp16.h>
#include <math.h>
#include <stdint.h>

#define HID   1024
#define EMBD  512
#define BATCH 64
#define SEQ   512
#define G4    4096
#define NBLK  128

// ===================== device scratch =====================
__device__ float    g_xproj[(size_t)SEQ * BATCH * G4];     // [t][b][4096]
// W_hh fp16, m16n8k16 B-fragment order (single plane):
//   u32 idx = (((jj*64 + s)*4 + g)*32 + lane)*2 + khalf
__device__ uint32_t g_wfrag16[128 * 64 * 4 * 32 * 2];      // 4 MB
// W_ih fp16 B-fragment order (single plane):
//   u32 idx = ((ntile*32 + s)*32 + lane)*2 + khalf
__device__ uint32_t g_wihfrag[512 * 32 * 32 * 2];          // 4 MB
// emb rows in A-fragment order, fp16 hi/lo (lo unscaled):
//   uint4 idx = ((mtile*32 + s)*32 + lane)*2 + part
__device__ uint4    g_afrag[2048 * 32 * 32 * 2];           // 67 MB
// h in A-fragment order, fp16: part0 = hi, part1 = (h-hi)*2048; double buffered
__device__ uint32_t g_hfrag[2][64 * 4 * 32 * 8];           // 512 KB x2
__device__ float    g_hfin[BATCH * HID];
__device__ unsigned g_count;

__global__ void init_kernel() {
    if (blockIdx.x == 0 && threadIdx.x == 0) g_count = 0u;
}

// ===================== helpers =====================
__device__ __forceinline__ float sigmf(float v) { return 1.0f / (1.0f + expf(-v)); }

__device__ __forceinline__ uint32_t pack_f16x2(float e0, float e1) {
    __half2 h = __floats2half2_rn(e0, e1);
    return *(uint32_t*)&h;
}
__device__ __forceinline__ float f16val(float v) {
    return __half2float(__float2half_rn(v));
}

#define MMA_F16(d, a, b0, b1) \
    asm volatile("mma.sync.aligned.m16n8k16.row.col.f32.f16.f16.f32 " \
        "{%0,%1,%2,%3}, {%4,%5,%6,%7}, {%8,%9}, {%0,%1,%2,%3};" \
        : "+f"((d)[0]), "+f"((d)[1]), "+f"((d)[2]), "+f"((d)[3]) \
        : "r"((a).x), "r"((a).y), "r"((a).z), "r"((a).w), "r"(b0), "r"(b1))

// ===================== W_hh -> fp16 fragment converter =====================
__global__ void wconv_kernel(const float* __restrict__ W_hh) {
    int id = blockIdx.x * blockDim.x + threadIdx.x;   // 4096*512 (n, k-pair)
    if (id >= 4096 * 512) return;
    int n  = id >> 9;
    int k  = (id & 511) * 2;
    float2 w = *(const float2*)(W_hh + (size_t)n * HID + k);

    int g  = n >> 10, jj = (n >> 3) & 127, ul = n & 7;
    int s  = k >> 4, tig = (k >> 1) & 3, khalf = (k >> 3) & 1;
    int lane = (ul << 2) | tig;
    uint32_t base = (uint32_t)((((jj * 64 + s) * 4 + g) * 32 + lane) * 2 + khalf);
    g_wfrag16[base] = pack_f16x2(w.x, w.y);
}

// ===================== W_ih -> fp16 fragment converter =====================
__global__ void wihconv_kernel(const float* __restrict__ W_ih) {
    int id = blockIdx.x * blockDim.x + threadIdx.x;   // 4096*256 k-pairs
    if (id >= 4096 * 256) return;
    int n  = id >> 8;
    int k  = (id & 255) * 2;
    float2 w = *(const float2*)(W_ih + (size_t)n * EMBD + k);

    int ntile = n >> 3, ul = n & 7;
    int s = k >> 4, tig = (k >> 1) & 3, khalf = (k >> 3) & 1;
    int lane = (ul << 2) | tig;
    uint32_t base = (uint32_t)(((ntile * 32 + s) * 32 + lane) * 2 + khalf);
    g_wihfrag[base] = pack_f16x2(w.x, w.y);
}

// ===================== embedding gather -> fp16 A fragments =====================
__global__ void gather_kernel(const int*   __restrict__ x,
                              const float* __restrict__ emb_table) {
    __shared__ int toks[16];
    const int mtile = blockIdx.x;
    const int tid = threadIdx.x;
    const int wid = tid >> 5;
    const int lid = tid & 31;

    if (tid < 16) {
        int m = mtile * 16 + tid;
        int t = m >> 6, b = m & 63;
        toks[tid] = x[b * SEQ + t];
    }
    __syncthreads();

    const int r0 = lid >> 2;
    const int c0 = (lid & 3) * 2;
    const int tok0 = toks[r0];
    const int tok1 = toks[r0 + 8];
    const float* e0 = emb_table + (size_t)tok0 * EMBD;
    const float* e1 = emb_table + (size_t)tok1 * EMBD;

#pragma unroll
    for (int q = 0; q < 4; q++) {
        int s = wid * 4 + q;
        int kb = s * 16;
        float2 v00 = (tok0 == 0) ? make_float2(0.f, 0.f) : *(const float2*)(e0 + kb + c0);
        float2 v01 = (tok0 == 0) ? make_float2(0.f, 0.f) : *(const float2*)(e0 + kb + c0 + 8);
        float2 v10 = (tok1 == 0) ? make_float2(0.f, 0.f) : *(const float2*)(e1 + kb + c0);
        float2 v11 = (tok1 == 0) ? make_float2(0.f, 0.f) : *(const float2*)(e1 + kb + c0 + 8);

        uint4 hi, lo;
        hi.x = pack_f16x2(v00.x, v00.y);
        hi.y = pack_f16x2(v10.x, v10.y);
        hi.z = pack_f16x2(v01.x, v01.y);
        hi.w = pack_f16x2(v11.x, v11.y);
        lo.x = pack_f16x2(v00.x - f16val(v00.x), v00.y - f16val(v00.y));
        lo.y = pack_f16x2(v10.x - f16val(v10.x), v10.y - f16val(v10.y));
        lo.z = pack_f16x2(v01.x - f16val(v01.x), v01.y - f16val(v01.y));
        lo.w = pack_f16x2(v11.x - f16val(v11.x), v11.y - f16val(v11.y));

        uint4* dst = g_afrag + (((size_t)mtile * 32 + s) * 32 + lid) * 2;
        dst[0] = hi;
        dst[1] = lo;
    }
}

// ===================== xproj GEMM (fp16 HMMA, 2-MMA split, nf=32) =====================
// M=32768, N=4096, K=512. grid (256, 16), 8 warps.
__global__ void __launch_bounds__(256, 1)
xproj_mma(const float* __restrict__ b_ih) {
    const int tid = threadIdx.x;
    const int wid = tid >> 5;
    const int lid = tid & 31;
    const int mtile = blockIdx.x * 8 + wid;
    const int nt0   = blockIdx.y * 32;

    float acc[32][4];
#pragma unroll
    for (int nf = 0; nf < 32; nf++)
#pragma unroll
        for (int c = 0; c < 4; c++) acc[nf][c] = 0.0f;

    const uint4* abase = g_afrag + ((size_t)mtile * 32) * 32 * 2 + lid * 2;
    const uint2* bbase = ((const uint2*)g_wihfrag) + ((size_t)nt0 * 32) * 32 + lid;

    for (int s = 0; s < 32; s++) {
        uint4 Ah = __ldcg(abase + (size_t)s * 64);
        uint4 Al = __ldcg(abase + (size_t)s * 64 + 1);
        const uint2* bp = bbase + (size_t)s * 32;
#pragma unroll
        for (int nf = 0; nf < 32; nf++) {
            uint2 B = __ldg(bp + (size_t)nf * 32 * 32);
            MMA_F16(acc[nf], Ah, B.x, B.y);
            MMA_F16(acc[nf], Al, B.x, B.y);
        }
    }

    const int row0 = mtile * 16 + (lid >> 2);
    const int cbase = (lid & 3) * 2;
    float* o0 = g_xproj + (size_t)row0 * G4;
    float* o1 = g_xproj + (size_t)(row0 + 8) * G4;
#pragma unroll
    for (int nf = 0; nf < 32; nf++) {
        int col = (nt0 + nf) * 8 + cbase;
        float2 bias = *(const float2*)(b_ih + col);
        *(float2*)(o0 + col) = make_float2(acc[nf][0] + bias.x, acc[nf][1] + bias.y);
        *(float2*)(o1 + col) = make_float2(acc[nf][2] + bias.x, acc[nf][3] + bias.y);
    }
}

// ===================== grid barrier (release/acquire) =====================
__device__ __forceinline__ void grid_bar(unsigned target) {
    __syncthreads();
    if (threadIdx.x == 0) {
        asm volatile("red.release.gpu.global.add.u32 [%0], %1;"
                     :: "l"(&g_count), "r"(1u) : "memory");
        unsigned v;
        while (true) {
            asm volatile("ld.acquire.gpu.global.u32 %0, [%1];"
                         : "=r"(v) : "l"(&g_count) : "memory");
            if (v >= target * NBLK) break;
            __nanosleep(32);
        }
    }
    __syncthreads();
}

// ===================== persistent LSTM recurrence (fp16 HMMA, 16-warp 4-way K-split)
// Block j owns gate cols {g*1024 + j*8 + ul}. Warp wid = kh*4 + mt.
// gates = acc1 + acc2/2048, acc1 = A_hi.W, acc2 = (A_lo*2048).W (fp32 accum).
__global__ void __launch_bounds__(512, 1)
lstm_persistent(const float* __restrict__ b_hh) {
    __shared__ float xs[64][36];
    __shared__ float psum[3][4][16][32];
    __shared__ float bhs[32];

    const int j   = blockIdx.x;
    const int tid = threadIdx.x;
    const int wid = tid >> 5;
    const int lid = tid & 31;
    const int kh  = wid >> 2;              // K-quarter 0..3
    const int mt  = wid & 3;               // m-tile
    const int r0  = mt * 16 + (lid >> 2);
    const int tig = lid & 3;
    const int sj  = j >> 1;
    const int regbase = (j & 1) << 1;

    if (tid < 32) {
        int g = tid >> 3, ul = tid & 7;
        bhs[tid] = b_hh[g * HID + j * 8 + ul];
    }

    if (wid < 4) {
        uint32_t* hb = g_hfrag[0] + (((sj * 4 + wid) * 32 + lid) * 8);
#pragma unroll
        for (int mh = 0; mh < 2; mh++) {
            hb[regbase + mh]     = 0u;
            hb[4 + regbase + mh] = 0u;
        }
    }
    float creg[4];
#pragma unroll
    for (int q = 0; q < 4; q++) creg[q] = 0.0f;

    unsigned barnum = 0;
    grid_bar(++barnum);

    // B-fragment base for this warp's K-quarter (uint2; per-s stride 128, per-g 32)
    const uint2* wbase = ((const uint2*)g_wfrag16)
                       + ((size_t)j * 64 + kh * 16) * 128 + lid;

    for (int t = 0; t < SEQ; t++) {
        const int cb = t & 1, nb = cb ^ 1;

        // ---- warps 8-15 stage x_proj tile [64 b x 32 cols] into smem
        if (wid >= 8) {
            int t2 = tid - 256;            // 0..255
            int b = t2 >> 2;               // 0..63
            int g = t2 & 3;                // gate
            const float* xp = g_xproj + (size_t)t * BATCH * G4 + (size_t)b * G4
                            + (size_t)g * HID + j * 8;
            float4 v0 = __ldcs((const float4*)xp);
            float4 v1 = __ldcs((const float4*)xp + 1);
            *(float4*)&xs[b][g * 8]     = v0;
            *(float4*)&xs[b][g * 8 + 4] = v1;
        }

        // ---- K-quarter loop: 16 k-steps of m16n8k16 fp16, 2 mma per g
        const uint4* habase = ((const uint4*)g_hfrag[cb])
                            + ((size_t)(kh * 64 + mt)) * 64 + lid * 2;
        uint4 Ab[4][2];       // ring, fill distance 3
        uint2 Bb[2][4];       // ring, fill distance 1
        float acc1[4][4], acc2[4][4];
#pragma unroll
        for (int g = 0; g < 4; g++)
#pragma unroll
            for (int c = 0; c < 4; c++) { acc1[g][c] = 0.0f; acc2[g][c] = 0.0f; }

#pragma unroll
        for (int p = 0; p < 3; p++) {
            const uint4* ap = habase + (size_t)p * 256;
            Ab[p][0] = __ldcg(ap);
            Ab[p][1] = __ldcg(ap + 1);
        }
#pragma unroll
        for (int g = 0; g < 4; g++) Bb[0][g] = __ldg(wbase + g * 32);

#pragma unroll
        for (int s = 0; s < 16; s++) {
            if (s < 15) {
                const uint2* wp = wbase + (size_t)(s + 1) * 128;
#pragma unroll
                for (int g = 0; g < 4; g++) Bb[(s + 1) & 1][g] = __ldg(wp + g * 32);
            }
            if (s < 13) {
                const uint4* ap = habase + (size_t)(s + 3) * 256;
                Ab[(s + 3) & 3][0] = __ldcg(ap);
                Ab[(s + 3) & 3][1] = __ldcg(ap + 1);
            }
            uint4 A0 = Ab[s & 3][0];
            uint4 A1 = Ab[s & 3][1];
#pragma unroll
            for (int g = 0; g < 4; g++) {
                uint2 B = Bb[s & 1][g];
                MMA_F16(acc1[g], A0, B.x, B.y);
                MMA_F16(acc2[g], A1, B.x, B.y);
            }
        }

        // combine scaled-lo accumulator
        float gf[4][4];
#pragma unroll
        for (int g = 0; g < 4; g++)
#pragma unroll
            for (int c = 0; c < 4; c++)
                gf[g][c] = acc1[g][c] + acc2[g][c] * (1.0f / 2048.0f);

        // ---- warps kh>=1: partials -> smem
        if (kh >= 1) {
#pragma unroll
            for (int g = 0; g < 4; g++)
#pragma unroll
                for (int c = 0; c < 4; c++)
                    psum[kh - 1][mt][g * 4 + c][lid] = gf[g][c];
        }
        __syncthreads();

        // ---- warps kh==0: reduce + LSTM update
        if (kh == 0) {
#pragma unroll
            for (int q = 0; q < 3; q++)
#pragma unroll
                for (int g = 0; g < 4; g++)
#pragma unroll
                    for (int c = 0; c < 4; c++)
                        gf[g][c] += psum[q][mt][g * 4 + c][lid];

            uint32_t* hb = g_hfrag[nb] + (((sj * 4 + mt) * 32 + lid) * 8);
#pragma unroll
            for (int mh = 0; mh < 2; mh++) {
                int row = r0 + 8 * mh;
                float h2[2];
#pragma unroll
                for (int cbit = 0; cbit < 2; cbit++) {
                    int ci = mh * 2 + cbit;
                    int ul = 2 * tig + cbit;
                    float ig = gf[0][ci] + xs[row][ul]      + bhs[ul];
                    float fg = gf[1][ci] + xs[row][8 + ul]  + bhs[8 + ul];
                    float gg = gf[2][ci] + xs[row][16 + ul] + bhs[16 + ul];
                    float og = gf[3][ci] + xs[row][24 + ul] + bhs[24 + ul];
                    float cn = sigmf(fg) * creg[ci] + sigmf(ig) * tanhf(gg);
                    creg[ci] = cn;
                    h2[cbit] = sigmf(og) * tanhf(cn);
                }
                float hi0 = f16val(h2[0]);
                float hi1 = f16val(h2[1]);
                hb[regbase + mh]     = pack_f16x2(h2[0], h2[1]);
                hb[4 + regbase + mh] = pack_f16x2((h2[0] - hi0) * 2048.0f,
                                                  (h2[1] - hi1) * 2048.0f);
                if (t == SEQ - 1) {
                    *(float2*)(g_hfin + row * HID + j * 8 + 2 * tig) =
                        make_float2(h2[0], h2[1]);
                }
            }
        }
        grid_bar(++barnum);
    }
}

// ===================== head (parallel warp-reduce) =====================
__global__ void final_kernel(const float* __restrict__ W1,
                             const float* __restrict__ b1,
                             const float* __restrict__ W2,
                             const float* __restrict__ b2,
                             float* __restrict__ out) {
    __shared__ float hidden[64];
    const int b   = blockIdx.x;
    const int tid = threadIdx.x;
    const int wid = tid >> 5;
    const int lid = tid & 31;
    const float* hrow = g_hfin + b * HID;

#pragma unroll
    for (int q = 0; q < 8; q++) {
        int jj = wid + q * 8;
        const float* wrow = W1 + jj * HID;
        float s = 0.0f;
#pragma unroll 8
        for (int k = lid; k < HID; k += 32) s = fmaf(hrow[k], wrow[k], s);
#pragma unroll
        for (int o = 16; o; o >>= 1) s += __shfl_xor_sync(0xFFFFFFFFu, s, o);
        if (lid == 0) hidden[jj] = fmaxf(s + b1[jj], 0.0f) * W2[jj];
    }
    __syncthreads();
    if (wid == 0) {
        float v = hidden[lid] + hidden[lid + 32];
#pragma unroll
        for (int o = 16; o; o >>= 1) v += __shfl_xor_sync(0xFFFFFFFFu, v, o);
        if (lid == 0) out[b] = v + b2[0];
    }
}

// ===================== launch =====================
extern "C" void kernel_launch(void* const* d_in, const int* in_sizes, int n_in,
                              void* d_out, int out_size) {
    (void)in_sizes; (void)n_in; (void)out_size;
    const int*   x         = (const int*)  d_in[0];
    const float* emb_table = (const float*)d_in[2];
    const float* W_ih      = (const float*)d_in[3];
    const float* b_ih      = (const float*)d_in[4];
    const float* W_hh      = (const float*)d_in[5];
    const float* b_hh      = (const float*)d_in[6];
    const float* W1        = (const float*)d_in[7];
    const float* b1        = (const float*)d_in[8];
    const float* W2        = (const float*)d_in[9];
    const float* b2        = (const float*)d_in[10];
    float* out = (float*)d_out;

    init_kernel<<<1, 32>>>();
    wconv_kernel<<<(4096 * 512 + 255) / 256, 256>>>(W_hh);
    wihconv_kernel<<<(4096 * 256 + 255) / 256, 256>>>(W_ih);
    gather_kernel<<<2048, 256>>>(x, emb_table);
    xproj_mma<<<dim3(256, 16), 256>>>(b_ih);
    lstm_persistent<<<NBLK, 512>>>(b_hh);
    final_kernel<<<BATCH, 256>>>(W1, b1, W2, b2, out);
}

// round 12
// speedup vs baseline: 2.1800x; 1.0604x over previous
#include <cuda_runtime.h>
#include <cuda_fp16.h>
#include <math.h>
#include <stdint.h>

#define HID   1024
#define EMBD  512
#define BATCH 64
#define SEQ   512
#define G4    4096
#define NBLK  128

// ===================== device scratch =====================
__device__ float    g_xproj[(size_t)SEQ * BATCH * G4];     // [t][b][4096]
// W_hh fp16, m16n8k16 B-fragment order (single plane):
//   u32 idx = (((jj*64 + s)*4 + g)*32 + lane)*2 + khalf
__device__ uint32_t g_wfrag16[128 * 64 * 4 * 32 * 2];      // 4 MB
// W_ih fp16 B-fragment order (single plane):
__device__ uint32_t g_wihfrag[512 * 32 * 32 * 2];          // 4 MB
// emb rows in A-fragment order, fp16 single plane:
//   uint4 idx = (mtile*32 + s)*32 + lane
__device__ uint4    g_afrag[2048 * 32 * 32];               // 33 MB
// h in A-fragment order, fp16: part0 = hi, part1 = (h-hi)*2048; double buffered
__device__ uint32_t g_hfrag[2][64 * 4 * 32 * 8];           // 512 KB x2
__device__ float    g_hfin[BATCH * HID];
__device__ unsigned g_count;

__global__ void init_kernel() {
    if (blockIdx.x == 0 && threadIdx.x == 0) g_count = 0u;
}

// ===================== helpers =====================
__device__ __forceinline__ float sigmf(float v) { return 1.0f / (1.0f + expf(-v)); }

__device__ __forceinline__ uint32_t pack_f16x2(float e0, float e1) {
    __half2 h = __floats2half2_rn(e0, e1);
    return *(uint32_t*)&h;
}
__device__ __forceinline__ float f16val(float v) {
    return __half2float(__float2half_rn(v));
}

#define MMA_F16(d, a, b0, b1) \
    asm volatile("mma.sync.aligned.m16n8k16.row.col.f32.f16.f16.f32 " \
        "{%0,%1,%2,%3}, {%4,%5,%6,%7}, {%8,%9}, {%0,%1,%2,%3};" \
        : "+f"((d)[0]), "+f"((d)[1]), "+f"((d)[2]), "+f"((d)[3]) \
        : "r"((a).x), "r"((a).y), "r"((a).z), "r"((a).w), "r"(b0), "r"(b1))

// ===================== W_hh -> fp16 fragment converter =====================
__global__ void wconv_kernel(const float* __restrict__ W_hh) {
    int id = blockIdx.x * blockDim.x + threadIdx.x;   // 4096*512 (n, k-pair)
    if (id >= 4096 * 512) return;
    int n  = id >> 9;
    int k  = (id & 511) * 2;
    float2 w = *(const float2*)(W_hh + (size_t)n * HID + k);

    int g  = n >> 10, jj = (n >> 3) & 127, ul = n & 7;
    int s  = k >> 4, tig = (k >> 1) & 3, khalf = (k >> 3) & 1;
    int lane = (ul << 2) | tig;
    uint32_t base = (uint32_t)((((jj * 64 + s) * 4 + g) * 32 + lane) * 2 + khalf);
    g_wfrag16[base] = pack_f16x2(w.x, w.y);
}

// ===================== W_ih -> fp16 fragment converter =====================
__global__ void wihconv_kernel(const float* __restrict__ W_ih) {
    int id = blockIdx.x * blockDim.x + threadIdx.x;   // 4096*256 k-pairs
    if (id >= 4096 * 256) return;
    int n  = id >> 8;
    int k  = (id & 255) * 2;
    float2 w = *(const float2*)(W_ih + (size_t)n * EMBD + k);

    int ntile = n >> 3, ul = n & 7;
    int s = k >> 4, tig = (k >> 1) & 3, khalf = (k >> 3) & 1;
    int lane = (ul << 2) | tig;
    uint32_t base = (uint32_t)(((ntile * 32 + s) * 32 + lane) * 2 + khalf);
    g_wihfrag[base] = pack_f16x2(w.x, w.y);
}

// ===================== embedding gather -> fp16 A fragments (1 plane) ==========
__global__ void gather_kernel(const int*   __restrict__ x,
                              const float* __restrict__ emb_table) {
    __shared__ int toks[16];
    const int mtile = blockIdx.x;
    const int tid = threadIdx.x;
    const int wid = tid >> 5;
    const int lid = tid & 31;

    if (tid < 16) {
        int m = mtile * 16 + tid;
        int t = m >> 6, b = m & 63;
        toks[tid] = x[b * SEQ + t];
    }
    __syncthreads();

    const int r0 = lid >> 2;
    const int c0 = (lid & 3) * 2;
    const int tok0 = toks[r0];
    const int tok1 = toks[r0 + 8];
    const float* e0 = emb_table + (size_t)tok0 * EMBD;
    const float* e1 = emb_table + (size_t)tok1 * EMBD;

#pragma unroll
    for (int q = 0; q < 4; q++) {
        int s = wid * 4 + q;
        int kb = s * 16;
        float2 v00 = (tok0 == 0) ? make_float2(0.f, 0.f) : *(const float2*)(e0 + kb + c0);
        float2 v01 = (tok0 == 0) ? make_float2(0.f, 0.f) : *(const float2*)(e0 + kb + c0 + 8);
        float2 v10 = (tok1 == 0) ? make_float2(0.f, 0.f) : *(const float2*)(e1 + kb + c0);
        float2 v11 = (tok1 == 0) ? make_float2(0.f, 0.f) : *(const float2*)(e1 + kb + c0 + 8);

        uint4 hi;
        hi.x = pack_f16x2(v00.x, v00.y);
        hi.y = pack_f16x2(v10.x, v10.y);
        hi.z = pack_f16x2(v01.x, v01.y);
        hi.w = pack_f16x2(v11.x, v11.y);

        g_afrag[((size_t)mtile * 32 + s) * 32 + lid] = hi;
    }
}

// ===================== xproj GEMM (fp16 HMMA, 1 MMA per k16, nf=32) ==============
// M=32768, N=4096, K=512. grid (256, 16), 8 warps.
__global__ void __launch_bounds__(256, 1)
xproj_mma(const float* __restrict__ b_ih) {
    const int tid = threadIdx.x;
    const int wid = tid >> 5;
    const int lid = tid & 31;
    const int mtile = blockIdx.x * 8 + wid;
    const int nt0   = blockIdx.y * 32;

    float acc[32][4];
#pragma unroll
    for (int nf = 0; nf < 32; nf++)
#pragma unroll
        for (int c = 0; c < 4; c++) acc[nf][c] = 0.0f;

    const uint4* abase = g_afrag + ((size_t)mtile * 32) * 32 + lid;
    const uint2* bbase = ((const uint2*)g_wihfrag) + ((size_t)nt0 * 32) * 32 + lid;

    for (int s = 0; s < 32; s++) {
        uint4 Ah = __ldcg(abase + (size_t)s * 32);
        const uint2* bp = bbase + (size_t)s * 32;
#pragma unroll
        for (int nf = 0; nf < 32; nf++) {
            uint2 B = __ldg(bp + (size_t)nf * 32 * 32);
            MMA_F16(acc[nf], Ah, B.x, B.y);
        }
    }

    const int row0 = mtile * 16 + (lid >> 2);
    const int cbase = (lid & 3) * 2;
    float* o0 = g_xproj + (size_t)row0 * G4;
    float* o1 = g_xproj + (size_t)(row0 + 8) * G4;
#pragma unroll
    for (int nf = 0; nf < 32; nf++) {
        int col = (nt0 + nf) * 8 + cbase;
        float2 bias = *(const float2*)(b_ih + col);
        *(float2*)(o0 + col) = make_float2(acc[nf][0] + bias.x, acc[nf][1] + bias.y);
        *(float2*)(o1 + col) = make_float2(acc[nf][2] + bias.x, acc[nf][3] + bias.y);
    }
}

// ===================== grid barrier (release/acquire) =====================
__device__ __forceinline__ void grid_bar(unsigned target) {
    __syncthreads();
    if (threadIdx.x == 0) {
        asm volatile("red.release.gpu.global.add.u32 [%0], %1;"
                     :: "l"(&g_count), "r"(1u) : "memory");
        unsigned v;
        while (true) {
            asm volatile("ld.acquire.gpu.global.u32 %0, [%1];"
                         : "=r"(v) : "l"(&g_count) : "memory");
            if (v >= target * NBLK) break;
            __nanosleep(32);
        }
    }
    __syncthreads();
}

// ===================== persistent LSTM recurrence (fp16 HMMA, 16-warp 4-way K-split)
// gates = acc1 + acc2/2048, acc1 = A_hi.W, acc2 = (A_lo*2048).W (fp32 accum).
// IDENTICAL to round-10 passing version.
__global__ void __launch_bounds__(512, 1)
lstm_persistent(const float* __restrict__ b_hh) {
    __shared__ float xs[64][36];
    __shared__ float psum[3][4][16][32];
    __shared__ float bhs[32];

    const int j   = blockIdx.x;
    const int tid = threadIdx.x;
    const int wid = tid >> 5;
    const int lid = tid & 31;
    const int kh  = wid >> 2;              // K-quarter 0..3
    const int mt  = wid & 3;               // m-tile
    const int r0  = mt * 16 + (lid >> 2);
    const int tig = lid & 3;
    const int sj  = j >> 1;
    const int regbase = (j & 1) << 1;

    if (tid < 32) {
        int g = tid >> 3, ul = tid & 7;
        bhs[tid] = b_hh[g * HID + j * 8 + ul];
    }

    if (wid < 4) {
        uint32_t* hb = g_hfrag[0] + (((sj * 4 + wid) * 32 + lid) * 8);
#pragma unroll
        for (int mh = 0; mh < 2; mh++) {
            hb[regbase + mh]     = 0u;
            hb[4 + regbase + mh] = 0u;
        }
    }
    float creg[4];
#pragma unroll
    for (int q = 0; q < 4; q++) creg[q] = 0.0f;

    unsigned barnum = 0;
    grid_bar(++barnum);

    // B-fragment base for this warp's K-quarter (uint2; per-s stride 128, per-g 32)
    const uint2* wbase = ((const uint2*)g_wfrag16)
                       + ((size_t)j * 64 + kh * 16) * 128 + lid;

    for (int t = 0; t < SEQ; t++) {
        const int cb = t & 1, nb = cb ^ 1;

        // ---- warps 8-15 stage x_proj tile [64 b x 32 cols] into smem
        if (wid >= 8) {
            int t2 = tid - 256;            // 0..255
            int b = t2 >> 2;               // 0..63
            int g = t2 & 3;                // gate
            const float* xp = g_xproj + (size_t)t * BATCH * G4 + (size_t)b * G4
                            + (size_t)g * HID + j * 8;
            float4 v0 = __ldcs((const float4*)xp);
            float4 v1 = __ldcs((const float4*)xp + 1);
            *(float4*)&xs[b][g * 8]     = v0;
            *(float4*)&xs[b][g * 8 + 4] = v1;
        }

        // ---- K-quarter loop: 16 k-steps of m16n8k16 fp16, 2 mma per g
        const uint4* habase = ((const uint4*)g_hfrag[cb])
                            + ((size_t)(kh * 64 + mt)) * 64 + lid * 2;
        uint4 Ab[4][2];       // ring, fill distance 3
        uint2 Bb[2][4];       // ring, fill distance 1
        float acc1[4][4], acc2[4][4];
#pragma unroll
        for (int g = 0; g < 4; g++)
#pragma unroll
            for (int c = 0; c < 4; c++) { acc1[g][c] = 0.0f; acc2[g][c] = 0.0f; }

#pragma unroll
        for (int p = 0; p < 3; p++) {
            const uint4* ap = habase + (size_t)p * 256;
            Ab[p][0] = __ldcg(ap);
            Ab[p][1] = __ldcg(ap + 1);
        }
#pragma unroll
        for (int g = 0; g < 4; g++) Bb[0][g] = __ldg(wbase + g * 32);

#pragma unroll
        for (int s = 0; s < 16; s++) {
            if (s < 15) {
                const uint2* wp = wbase + (size_t)(s + 1) * 128;
#pragma unroll
                for (int g = 0; g < 4; g++) Bb[(s + 1) & 1][g] = __ldg(wp + g * 32);
            }
            if (s < 13) {
                const uint4* ap = habase + (size_t)(s + 3) * 256;
                Ab[(s + 3) & 3][0] = __ldcg(ap);
                Ab[(s + 3) & 3][1] = __ldcg(ap + 1);
            }
            uint4 A0 = Ab[s & 3][0];
            uint4 A1 = Ab[s & 3][1];
#pragma unroll
            for (int g = 0; g < 4; g++) {
                uint2 B = Bb[s & 1][g];
                MMA_F16(acc1[g], A0, B.x, B.y);
                MMA_F16(acc2[g], A1, B.x, B.y);
            }
        }

        // combine scaled-lo accumulator
        float gf[4][4];
#pragma unroll
        for (int g = 0; g < 4; g++)
#pragma unroll
            for (int c = 0; c < 4; c++)
                gf[g][c] = acc1[g][c] + acc2[g][c] * (1.0f / 2048.0f);

        // ---- warps kh>=1: partials -> smem
        if (kh >= 1) {
#pragma unroll
            for (int g = 0; g < 4; g++)
#pragma unroll
                for (int c = 0; c < 4; c++)
                    psum[kh - 1][mt][g * 4 + c][lid] = gf[g][c];
        }
        __syncthreads();

        // ---- warps kh==0: reduce + LSTM update
        if (kh == 0) {
#pragma unroll
            for (int q = 0; q < 3; q++)
#pragma unroll
                for (int g = 0; g < 4; g++)
#pragma unroll
                    for (int c = 0; c < 4; c++)
                        gf[g][c] += psum[q][mt][g * 4 + c][lid];

            uint32_t* hb = g_hfrag[nb] + (((sj * 4 + mt) * 32 + lid) * 8);
#pragma unroll
            for (int mh = 0; mh < 2; mh++) {
                int row = r0 + 8 * mh;
                float h2[2];
#pragma unroll
                for (int cbit = 0; cbit < 2; cbit++) {
                    int ci = mh * 2 + cbit;
                    int ul = 2 * tig + cbit;
                    float ig = gf[0][ci] + xs[row][ul]      + bhs[ul];
                    float fg = gf[1][ci] + xs[row][8 + ul]  + bhs[8 + ul];
                    float gg = gf[2][ci] + xs[row][16 + ul] + bhs[16 + ul];
                    float og = gf[3][ci] + xs[row][24 + ul] + bhs[24 + ul];
                    float cn = sigmf(fg) * creg[ci] + sigmf(ig) * tanhf(gg);
                    creg[ci] = cn;
                    h2[cbit] = sigmf(og) * tanhf(cn);
                }
                float hi0 = f16val(h2[0]);
                float hi1 = f16val(h2[1]);
                hb[regbase + mh]     = pack_f16x2(h2[0], h2[1]);
                hb[4 + regbase + mh] = pack_f16x2((h2[0] - hi0) * 2048.0f,
                                                  (h2[1] - hi1) * 2048.0f);
                if (t == SEQ - 1) {
                    *(float2*)(g_hfin + row * HID + j * 8 + 2 * tig) =
                        make_float2(h2[0], h2[1]);
                }
            }
        }
        grid_bar(++barnum);
    }
}

// ===================== head (parallel warp-reduce) =====================
__global__ void final_kernel(const float* __restrict__ W1,
                             const float* __restrict__ b1,
                             const float* __restrict__ W2,
                             const float* __restrict__ b2,
                             float* __restrict__ out) {
    __shared__ float hidden[64];
    const int b   = blockIdx.x;
    const int tid = threadIdx.x;
    const int wid = tid >> 5;
    const int lid = tid & 31;
    const float* hrow = g_hfin + b * HID;

#pragma unroll
    for (int q = 0; q < 8; q++) {
        int jj = wid + q * 8;
        const float* wrow = W1 + jj * HID;
        float s = 0.0f;
#pragma unroll 8
        for (int k = lid; k < HID; k += 32) s = fmaf(hrow[k], wrow[k], s);
#pragma unroll
        for (int o = 16; o; o >>= 1) s += __shfl_xor_sync(0xFFFFFFFFu, s, o);
        if (lid == 0) hidden[jj] = fmaxf(s + b1[jj], 0.0f) * W2[jj];
    }
    __syncthreads();
    if (wid == 0) {
        float v = hidden[lid] + hidden[lid + 32];
#pragma unroll
        for (int o = 16; o; o >>= 1) v += __shfl_xor_sync(0xFFFFFFFFu, v, o);
        if (lid == 0) out[b] = v + b2[0];
    }
}

// ===================== launch =====================
extern "C" void kernel_launch(void* const* d_in, const int* in_sizes, int n_in,
                              void* d_out, int out_size) {
    (void)in_sizes; (void)n_in; (void)out_size;
    const int*   x         = (const int*)  d_in[0];
    const float* emb_table = (const float*)d_in[2];
    const float* W_ih      = (const float*)d_in[3];
    const float* b_ih      = (const float*)d_in[4];
    const float* W_hh      = (const float*)d_in[5];
    const float* b_hh      = (const float*)d_in[6];
    const float* W1        = (const float*)d_in[7];
    const float* b1        = (const float*)d_in[8];
    const float* W2        = (const float*)d_in[9];
    const float* b2        = (const float*)d_in[10];
    float* out = (float*)d_out;

    init_kernel<<<1, 32>>>();
    wconv_kernel<<<(4096 * 512 + 255) / 256, 256>>>(W_hh);
    wihconv_kernel<<<(4096 * 256 + 255) / 256, 256>>>(W_ih);
    gather_kernel<<<2048, 256>>>(x, emb_table);
    xproj_mma<<<dim3(256, 16), 256>>>(b_ih);
    lstm_persistent<<<NBLK, 512>>>(b_hh);
    final_kernel<<<BATCH, 256>>>(W1, b1, W2, b2, out);
}